// round 9
// baseline (speedup 1.0000x reference)
#include <cuda_runtime.h>
#include <cuda_fp16.h>
#include <cstdint>

#define N_NODES 4096
#define IN_F    512
#define NHEADS  4
#define OUT_F   64
#define C_TOT   256
#define ALPHA   0.2f
#define ESHIFT  2.0f

// ---------------- scratch ----------------
// H in fragment-major order: u32[ head ][ kblk(256) ][ nb(8) ][ lane(32)*2+reg ]
// value(reg,sub): B[k = kblk*16 + reg*8 + tig*2 + sub][n = nb*8 + gid]  (fp16 pair)
__device__ uint32_t g_hF  [NHEADS * 256 * 8 * 64];
__device__ float    g_WT  [C_TOT * IN_F];         // W^T, pre-rounded to tf32
__device__ __half2  g_esh [NHEADS * N_NODES];     // (exp(s-2), exp(a*s-2))  i-side
__device__ __half2  g_ee  [NHEADS * N_NODES];     // (exp(t-2), exp(a*t-2))  j-side
__device__ uint32_t g_adjbits[N_NODES * (N_NODES / 32)];

// ---------------- helpers ----------------
__device__ __forceinline__ uint32_t f2tf32(float f) {
    uint32_t u;
    asm("cvt.rna.tf32.f32 %0, %1;" : "=r"(u) : "f"(f));
    return u;
}
__device__ __forceinline__ uint32_t hmul2u(uint32_t a, uint32_t b) {
    uint32_t r; asm("mul.f16x2 %0, %1, %2;" : "=r"(r) : "r"(a), "r"(b)); return r;
}
__device__ __forceinline__ uint32_t hmax2u(uint32_t a, uint32_t b) {
    uint32_t r; asm("max.f16x2 %0, %1, %2;" : "=r"(r) : "r"(a), "r"(b)); return r;
}
__device__ __forceinline__ void mma_tf32_16n8k8(float* d, const uint32_t* a,
                                                uint32_t b0, uint32_t b1) {
    asm volatile(
        "mma.sync.aligned.m16n8k8.row.col.f32.tf32.tf32.f32 "
        "{%0,%1,%2,%3}, {%4,%5,%6,%7}, {%8,%9}, {%0,%1,%2,%3};"
        : "+f"(d[0]), "+f"(d[1]), "+f"(d[2]), "+f"(d[3])
        : "r"(a[0]), "r"(a[1]), "r"(a[2]), "r"(a[3]), "r"(b0), "r"(b1));
}
__device__ __forceinline__ void mma_f16_16n8k16(float* d, const uint32_t* a,
                                                uint32_t b0, uint32_t b1) {
    asm volatile(
        "mma.sync.aligned.m16n8k16.row.col.f32.f16.f16.f32 "
        "{%0,%1,%2,%3}, {%4,%5,%6,%7}, {%8,%9}, {%0,%1,%2,%3};"
        : "+f"(d[0]), "+f"(d[1]), "+f"(d[2]), "+f"(d[3])
        : "r"(a[0]), "r"(a[1]), "r"(a[2]), "r"(a[3]), "r"(b0), "r"(b1));
}

// ---------------- kernel 0: transpose W -> g_WT (pre-tf32) ----------------
__global__ __launch_bounds__(256) void transpose_w(const float* __restrict__ W) {
    __shared__ float t[32][33];
    int kx = blockIdx.x * 32, nx = blockIdx.y * 32;
    int lx = threadIdx.x & 31, ly = threadIdx.x >> 5;
    #pragma unroll
    for (int q = 0; q < 4; q++)
        t[ly + q*8][lx] = W[(kx + ly + q*8) * C_TOT + nx + lx];
    __syncthreads();
    #pragma unroll
    for (int q = 0; q < 4; q++)
        g_WT[(nx + ly + q*8) * IN_F + kx + lx] =
            __uint_as_float(f2tf32(t[lx][ly + q*8]));
}

// ---------------- kernel 1d: pack adj into bits ----------------
__global__ __launch_bounds__(256) void pack_adj(const int* __restrict__ adj) {
    int g = blockIdx.x * 256 + threadIdx.x;
    int w = g >> 5, lane = g & 31;
    int v = adj[w * 32 + lane];
    uint32_t b = __ballot_sync(0xffffffffu, v > 0);
    if (lane == 0) g_adjbits[w] = b;
}

// ---------------- kernel 1: h = x@W (tf32 HMMA, 512 thr) + fused epilogue ----
// Writes H directly in fragment-major order (g_hF) + exp factor tables.
__global__ __launch_bounds__(512) void gemm_xw_mma(const float* __restrict__ x,
                                                   const float* __restrict__ avec) {
    __shared__ uint32_t sA[128 * 36];     // reused as fp16 sT 64x136
    __shared__ uint32_t sB[64 * 36];      // reused as s_part
    __shared__ float s_a[128];

    int tid = threadIdx.x, wid = tid >> 5, lane = tid & 31;
    int gid = lane >> 2, tig = lane & 3;
    int mg = wid & 7, nh = wid >> 3;
    int wrow = mg * 16, ncol0 = nh * 32;
    int n0 = blockIdx.x * 64, m0 = blockIdx.y * 128;
    int head = blockIdx.x;

    if (tid < 128) s_a[tid] = avec[tid];

    float acc[4][4];
    #pragma unroll
    for (int nb = 0; nb < 4; nb++)
        #pragma unroll
        for (int q = 0; q < 4; q++) acc[nb][q] = 0.f;

    int ar = tid >> 2, aks = (tid & 3) * 8;
    int bn = tid >> 3, bks = (tid & 7) * 4;
    const float* aptr = &x[(m0 + ar) * IN_F + aks];
    const float* bptr = &g_WT[(n0 + bn) * IN_F + bks];

    float4 av[2]; uint4 bv;
    av[0] = *(const float4*)(aptr);
    av[1] = *(const float4*)(aptr + 4);
    bv = *(const uint4*)(bptr);

    for (int it = 0; it < 16; it++) {
        __syncthreads();
        #pragma unroll
        for (int e = 0; e < 2; e++) {
            uint4 u = { f2tf32(av[e].x), f2tf32(av[e].y), f2tf32(av[e].z), f2tf32(av[e].w) };
            *(uint4*)&sA[ar * 36 + aks + 4 * e] = u;
        }
        *(uint4*)&sB[bn * 36 + bks] = bv;
        if (it < 15) {
            int kk = (it + 1) * 32;
            av[0] = *(const float4*)(aptr + kk);
            av[1] = *(const float4*)(aptr + kk + 4);
            bv = *(const uint4*)(bptr + kk);
        }
        __syncthreads();

        #pragma unroll
        for (int kst = 0; kst < 4; kst++) {
            int k0 = kst * 8;
            uint32_t a[4];
            a[0] = sA[(wrow + gid)     * 36 + k0 + tig];
            a[1] = sA[(wrow + gid + 8) * 36 + k0 + tig];
            a[2] = sA[(wrow + gid)     * 36 + k0 + tig + 4];
            a[3] = sA[(wrow + gid + 8) * 36 + k0 + tig + 4];
            #pragma unroll
            for (int nb = 0; nb < 4; nb++) {
                uint32_t b0 = sB[(ncol0 + nb * 8 + gid) * 36 + k0 + tig];
                uint32_t b1 = sB[(ncol0 + nb * 8 + gid) * 36 + k0 + tig + 4];
                mma_tf32_16n8k8(acc[nb], a, b0, b1);
            }
        }
    }

    // ---- partial s,t dots over this warp's 32 cols ----
    float sp0 = 0.f, sp1 = 0.f, tp0 = 0.f, tp1 = 0.f;
    #pragma unroll
    for (int nb = 0; nb < 4; nb++) {
        int cb = ncol0 + nb * 8 + 2 * tig;
        float a0 = s_a[cb],      a1 = s_a[cb + 1];
        float d0 = s_a[64 + cb], d1 = s_a[64 + cb + 1];
        sp0 += acc[nb][0] * a0 + acc[nb][1] * a1;
        sp1 += acc[nb][2] * a0 + acc[nb][3] * a1;
        tp0 += acc[nb][0] * d0 + acc[nb][1] * d1;
        tp1 += acc[nb][2] * d0 + acc[nb][3] * d1;
    }
    #pragma unroll
    for (int o = 1; o < 4; o <<= 1) {
        sp0 += __shfl_xor_sync(0xffffffffu, sp0, o);
        sp1 += __shfl_xor_sync(0xffffffffu, sp1, o);
        tp0 += __shfl_xor_sync(0xffffffffu, tp0, o);
        tp1 += __shfl_xor_sync(0xffffffffu, tp1, o);
    }

    __syncthreads();
    float* s_part = (float*)sB;          // [128][2]
    if (nh == 1 && tig == 0) {
        s_part[(wrow + gid) * 2]         = sp0;
        s_part[(wrow + gid) * 2 + 1]     = tp0;
        s_part[(wrow + gid + 8) * 2]     = sp1;
        s_part[(wrow + gid + 8) * 2 + 1] = tp1;
    }
    // fp16 transposed stage into sT: [64 f][128 m] stride 136
    __half* sT = (__half*)sA;
    {
        int rlo = wrow + gid, rhi = rlo + 8;
        #pragma unroll
        for (int nb = 0; nb < 4; nb++) {
            int cb = ncol0 + nb * 8 + 2 * tig;
            sT[cb * 136 + rlo]       = __float2half_rn(acc[nb][0]);
            sT[(cb + 1) * 136 + rlo] = __float2half_rn(acc[nb][1]);
            sT[cb * 136 + rhi]       = __float2half_rn(acc[nb][2]);
            sT[(cb + 1) * 136 + rhi] = __float2half_rn(acc[nb][3]);
        }
    }
    __syncthreads();

    if (nh == 0 && tig == 0) {
        int r0 = wrow + gid, r1 = r0 + 8;
        float s0 = sp0 + s_part[r0 * 2], t0 = tp0 + s_part[r0 * 2 + 1];
        float s1 = sp1 + s_part[r1 * 2], t1 = tp1 + s_part[r1 * 2 + 1];
        int olo = head * N_NODES + m0 + r0, ohi = head * N_NODES + m0 + r1;
        g_esh[olo] = __floats2half2_rn(expf(s0 - ESHIFT), expf(ALPHA * s0 - ESHIFT));
        g_esh[ohi] = __floats2half2_rn(expf(s1 - ESHIFT), expf(ALPHA * s1 - ESHIFT));
        g_ee [olo] = __floats2half2_rn(expf(t0 - ESHIFT), expf(ALPHA * t0 - ESHIFT));
        g_ee [ohi] = __floats2half2_rn(expf(t1 - ESHIFT), expf(ALPHA * t1 - ESHIFT));
    }

    // ---- write fragment-major H ----
    // u32 index within this tile: u = kl*512 + nb*64 + lane*2 + reg  (kl 0..7)
    // value: halves at sT[(nb*8+gid)*136 + kl*16 + reg*8 + tig*2]
    uint32_t* hF = g_hF + head * 131072 + m0 * 32;
    #pragma unroll
    for (int rep = 0; rep < 2; rep++) {
        int u = (tid + rep * 512) * 4;
        int kl = u >> 9, nbw = (u >> 6) & 7, r = u & 63;
        uint32_t vals[4];
        #pragma unroll
        for (int e = 0; e < 4; e++) {
            int ln = (r + e) >> 1, reg = (r + e) & 1;
            int gw = ln >> 2, tw = ln & 3;
            int f = nbw * 8 + gw;
            int jl = kl * 16 + reg * 8 + tw * 2;
            vals[e] = *(const uint32_t*)&sT[f * 136 + jl];
        }
        *(uint4*)&hF[u] = make_uint4(vals[0], vals[1], vals[2], vals[3]);
    }
}

// ---------------- kernel 2: aggregation v4 — barrier-free main loop ----------
#define AGO_EE   0u          // 4096 half2 = 16384 B
#define AGO_ACC  16384u      // 128 x 66 f = 33792 B
#define AGO_RED  50176u      // 2 x 128 f
#define AGO_LI   51200u      // 128 f
#define SMEM_AGG 51712
#define ONESB    0x3C003C00u

__global__ __launch_bounds__(512, 1) void aggregate_v4(float* __restrict__ out) {
    extern __shared__ char smem[];
    const uint32_t* st_ee = (const uint32_t*)(smem + AGO_EE);
    float* sAcc  = (float*)(smem + AGO_ACC);
    float* sred  = (float*)(smem + AGO_RED);
    float* slinv = (float*)(smem + AGO_LI);

    int tid = threadIdx.x, wid = tid >> 5, lane = tid & 31;
    int gid = lane >> 2, tig = lane & 3;
    int h = blockIdx.x & 3, i0 = (blockIdx.x >> 2) * 128;
    int mg = wid & 7, ks = wid >> 3;
    int wrow = mg * 16, r0 = wrow + gid, r1 = r0 + 8;

    // stage j-side factor table (one-time)
    {
        const uint4* src = (const uint4*)&g_ee[h * N_NODES];
        uint4* dst = (uint4*)(smem + AGO_EE);
        dst[tid]       = src[tid];
        dst[tid + 512] = src[tid + 512];
    }
    uint32_t esh0 = *(const uint32_t*)&g_esh[h * N_NODES + i0 + r0];
    uint32_t esh1 = *(const uint32_t*)&g_esh[h * N_NODES + i0 + r1];
    const uint32_t* adj0 = &g_adjbits[(i0 + r0) * 128];
    const uint32_t* adj1 = &g_adjbits[(i0 + r1) * 128];
    const uint32_t* hF = g_hF + h * 131072;

    float acc[8][4], accl[4];
    #pragma unroll
    for (int nb = 0; nb < 8; nb++)
        #pragma unroll
        for (int e = 0; e < 4; e++) acc[nb][e] = 0.f;
    #pragma unroll
    for (int e = 0; e < 4; e++) accl[e] = 0.f;

    __syncthreads();   // ee table ready — LAST barrier before epilogue

    // step s = 0..127 : kblk = (s>>2)*8 + ks*4 + (s&3)   (16 j's per step)
    uint2 Bc[8], Bn[8];
    uint32_t w0c, w1c, w0n, w1n;
    {
        int kblk = ks * 4;
        const uint32_t* p = hF + kblk * 512 + lane * 2;
        #pragma unroll
        for (int nb = 0; nb < 8; nb++) Bc[nb] = *(const uint2*)(p + nb * 64);
        w0c = adj0[kblk >> 1];
        w1c = adj1[kblk >> 1];
    }

    for (int s = 0; s < 128; s++) {
        int kblk = ((s >> 2) << 3) + ks * 4 + (s & 3);
        // prefetch step s+1
        if (s < 127) {
            int nk = (((s + 1) >> 2) << 3) + ks * 4 + ((s + 1) & 3);
            const uint32_t* p = hF + nk * 512 + lane * 2;
            #pragma unroll
            for (int nb = 0; nb < 8; nb++) Bn[nb] = *(const uint2*)(p + nb * 64);
            w0n = adj0[nk >> 1];
            w1n = adj1[nk >> 1];
        }

        // ---- build A-fragment (16 k) : p = max(es*Et, eas*Eat), fp16x2 ----
        uint32_t afr[4];
        {
            uint32_t ws0 = w0c >> ((kblk & 1) * 16);
            uint32_t ws1 = w1c >> ((kblk & 1) * 16);
            int jb = kblk * 16;
            #pragma unroll
            for (int kp = 0; kp < 2; kp++) {
                int koff = kp * 8 + 2 * tig;
                uint2 ee2 = *(const uint2*)(st_ee + jb + koff);
                uint32_t pA = hmul2u(esh0, ee2.x), pB = hmul2u(esh0, ee2.y);
                uint32_t pk = hmax2u(__byte_perm(pA, pB, 0x5410),
                                     __byte_perm(pA, pB, 0x7632));
                uint32_t km = (((ws0 >> koff) & 1u) ? 0x0000FFFFu : 0u) |
                              (((ws0 >> koff) & 2u) ? 0xFFFF0000u : 0u);
                afr[2 * kp] = pk & km;
                pA = hmul2u(esh1, ee2.x); pB = hmul2u(esh1, ee2.y);
                pk = hmax2u(__byte_perm(pA, pB, 0x5410),
                            __byte_perm(pA, pB, 0x7632));
                km = (((ws1 >> koff) & 1u) ? 0x0000FFFFu : 0u) |
                     (((ws1 >> koff) & 2u) ? 0xFFFF0000u : 0u);
                afr[2 * kp + 1] = pk & km;
            }
        }

        // ---- 9 MMAs ----
        #pragma unroll
        for (int nb = 0; nb < 8; nb++)
            mma_f16_16n8k16(acc[nb], afr, Bc[nb].x, Bc[nb].y);
        mma_f16_16n8k16(accl, afr, ONESB, ONESB);

        // swap pipeline regs
        #pragma unroll
        for (int nb = 0; nb < 8; nb++) Bc[nb] = Bn[nb];
        w0c = w0n; w1c = w1n;
    }

    // ---- l from ones-MMA + k-split combine ----
    if (tig == 0) {
        sred[ks * 128 + r0] = accl[0];
        sred[ks * 128 + r1] = accl[2];
    }
    if (ks == 1) {
        #pragma unroll
        for (int nb = 0; nb < 8; nb++) {
            int cb = nb * 8 + 2 * tig;
            *(float2*)&sAcc[r0 * 66 + cb] = make_float2(acc[nb][0], acc[nb][1]);
            *(float2*)&sAcc[r1 * 66 + cb] = make_float2(acc[nb][2], acc[nb][3]);
        }
    }
    __syncthreads();
    if (tid < 128) slinv[tid] = 1.f / (sred[tid] + sred[128 + tid]);
    __syncthreads();

    if (ks == 0) {
        float inv0 = slinv[r0], inv1 = slinv[r1];
        #pragma unroll
        for (int nb = 0; nb < 8; nb++) {
            int cb = nb * 8 + 2 * tig;
            float2 o0 = *(const float2*)&sAcc[r0 * 66 + cb];
            float2 o1 = *(const float2*)&sAcc[r1 * 66 + cb];
            float2 v0 = make_float2((acc[nb][0] + o0.x) * inv0, (acc[nb][1] + o0.y) * inv0);
            float2 v1 = make_float2((acc[nb][2] + o1.x) * inv1, (acc[nb][3] + o1.y) * inv1);
            *(float2*)&out[(i0 + r0) * C_TOT + h * 64 + cb] = v0;
            *(float2*)&out[(i0 + r1) * C_TOT + h * 64 + cb] = v1;
        }
    }
}

// ---------------- launch ----------------
extern "C" void kernel_launch(void* const* d_in, const int* in_sizes, int n_in,
                              void* d_out, int out_size) {
    const float* x   = (const float*)d_in[0];
    const int*   adj = (const int*)  d_in[1];
    const float* W   = (const float*)d_in[2];
    const float* a   = (const float*)d_in[3];
    float* out = (float*)d_out;

    cudaFuncSetAttribute(aggregate_v4,
                         cudaFuncAttributeMaxDynamicSharedMemorySize, SMEM_AGG);

    pack_adj<<<(N_NODES * N_NODES) / 256, 256>>>(adj);
    transpose_w<<<dim3(IN_F / 32, C_TOT / 32), 256>>>(W);
    gemm_xw_mma<<<dim3(C_TOT / 64, N_NODES / 128), 512>>>(x, a);
    aggregate_v4<<<(N_NODES / 128) * NHEADS, 512, SMEM_AGG>>>(out);
}

// round 10
// speedup vs baseline: 1.0042x; 1.0042x over previous
#include <cuda_runtime.h>
#include <cuda_fp16.h>
#include <cstdint>

#define N_NODES 4096
#define IN_F    512
#define NHEADS  4
#define OUT_F   64
#define C_TOT   256
#define ALPHA   0.2f
#define ESHIFT  2.0f

// ---------------- scratch ----------------
__device__ __half   g_hT  [C_TOT * N_NODES];      // [(h*64+f)][j]  fp16
__device__ float    g_WT  [C_TOT * IN_F];         // W^T, pre-rounded to tf32
__device__ __half2  g_esh [NHEADS * N_NODES];     // (exp(s-2), exp(a*s-2))  i-side
__device__ __half2  g_ee  [NHEADS * N_NODES];     // (exp(t-2), exp(a*t-2))  j-side
__device__ uint32_t g_adjbits[N_NODES * (N_NODES / 32)];

// ---------------- helpers ----------------
__device__ __forceinline__ uint32_t smem_u32(const void* p) {
    uint32_t a;
    asm("{ .reg .u64 t; cvta.to.shared.u64 t, %1; cvt.u32.u64 %0, t; }"
        : "=r"(a) : "l"(p));
    return a;
}
__device__ __forceinline__ uint32_t f2tf32(float f) {
    uint32_t u;
    asm("cvt.rna.tf32.f32 %0, %1;" : "=r"(u) : "f"(f));
    return u;
}
__device__ __forceinline__ uint32_t hmul2u(uint32_t a, uint32_t b) {
    uint32_t r; asm("mul.f16x2 %0, %1, %2;" : "=r"(r) : "r"(a), "r"(b)); return r;
}
__device__ __forceinline__ uint32_t hmax2u(uint32_t a, uint32_t b) {
    uint32_t r; asm("max.f16x2 %0, %1, %2;" : "=r"(r) : "r"(a), "r"(b)); return r;
}
__device__ __forceinline__ void mma_tf32_16n8k8(float* d, const uint32_t* a,
                                                uint32_t b0, uint32_t b1) {
    asm volatile(
        "mma.sync.aligned.m16n8k8.row.col.f32.tf32.tf32.f32 "
        "{%0,%1,%2,%3}, {%4,%5,%6,%7}, {%8,%9}, {%0,%1,%2,%3};"
        : "+f"(d[0]), "+f"(d[1]), "+f"(d[2]), "+f"(d[3])
        : "r"(a[0]), "r"(a[1]), "r"(a[2]), "r"(a[3]), "r"(b0), "r"(b1));
}
__device__ __forceinline__ void mma_f16_16n8k16(float* d, const uint32_t* a,
                                                uint32_t b0, uint32_t b1) {
    asm volatile(
        "mma.sync.aligned.m16n8k16.row.col.f32.f16.f16.f32 "
        "{%0,%1,%2,%3}, {%4,%5,%6,%7}, {%8,%9}, {%0,%1,%2,%3};"
        : "+f"(d[0]), "+f"(d[1]), "+f"(d[2]), "+f"(d[3])
        : "r"(a[0]), "r"(a[1]), "r"(a[2]), "r"(a[3]), "r"(b0), "r"(b1));
}
__device__ __forceinline__ void ldmat_x4(uint32_t* r, uint32_t addr) {
    asm volatile("ldmatrix.sync.aligned.m8n8.x4.shared.b16 {%0,%1,%2,%3}, [%4];"
        : "=r"(r[0]), "=r"(r[1]), "=r"(r[2]), "=r"(r[3]) : "r"(addr));
}

// ---------------- kernel 0: transpose W -> g_WT (pre-tf32) ----------------
__global__ __launch_bounds__(256) void transpose_w(const float* __restrict__ W) {
    __shared__ float t[32][33];
    int kx = blockIdx.x * 32, nx = blockIdx.y * 32;
    int lx = threadIdx.x & 31, ly = threadIdx.x >> 5;
    #pragma unroll
    for (int q = 0; q < 4; q++)
        t[ly + q*8][lx] = W[(kx + ly + q*8) * C_TOT + nx + lx];
    __syncthreads();
    #pragma unroll
    for (int q = 0; q < 4; q++)
        g_WT[(nx + ly + q*8) * IN_F + kx + lx] =
            __uint_as_float(f2tf32(t[lx][ly + q*8]));
}

// ---------------- kernel 1d: pack adj into bits ----------------
__global__ __launch_bounds__(256) void pack_adj(const int* __restrict__ adj) {
    int g = blockIdx.x * 256 + threadIdx.x;
    int w = g >> 5, lane = g & 31;
    int v = adj[w * 32 + lane];
    uint32_t b = __ballot_sync(0xffffffffu, v > 0);
    if (lane == 0) g_adjbits[w] = b;
}

// ---------------- kernel 1: h = x@W (tf32 HMMA, 512 thr) + fused epilogue ----
__global__ __launch_bounds__(512) void gemm_xw_mma(const float* __restrict__ x,
                                                   const float* __restrict__ avec) {
    __shared__ uint32_t sA[128 * 36];     // reused as fp16 sT 64x136
    __shared__ uint32_t sB[64 * 36];      // reused as s_part
    __shared__ float s_a[128];

    int tid = threadIdx.x, wid = tid >> 5, lane = tid & 31;
    int gid = lane >> 2, tig = lane & 3;
    int mg = wid & 7, nh = wid >> 3;
    int wrow = mg * 16, ncol0 = nh * 32;
    int n0 = blockIdx.x * 64, m0 = blockIdx.y * 128;
    int head = blockIdx.x;

    if (tid < 128) s_a[tid] = avec[tid];

    float acc[4][4];
    #pragma unroll
    for (int nb = 0; nb < 4; nb++)
        #pragma unroll
        for (int q = 0; q < 4; q++) acc[nb][q] = 0.f;

    int ar = tid >> 2, aks = (tid & 3) * 8;
    int bn = tid >> 3, bks = (tid & 7) * 4;
    const float* aptr = &x[(m0 + ar) * IN_F + aks];
    const float* bptr = &g_WT[(n0 + bn) * IN_F + bks];

    float4 av[2]; uint4 bv;
    av[0] = *(const float4*)(aptr);
    av[1] = *(const float4*)(aptr + 4);
    bv = *(const uint4*)(bptr);

    for (int it = 0; it < 16; it++) {
        __syncthreads();
        #pragma unroll
        for (int e = 0; e < 2; e++) {
            uint4 u = { f2tf32(av[e].x), f2tf32(av[e].y), f2tf32(av[e].z), f2tf32(av[e].w) };
            *(uint4*)&sA[ar * 36 + aks + 4 * e] = u;
        }
        *(uint4*)&sB[bn * 36 + bks] = bv;
        if (it < 15) {
            int kk = (it + 1) * 32;
            av[0] = *(const float4*)(aptr + kk);
            av[1] = *(const float4*)(aptr + kk + 4);
            bv = *(const uint4*)(bptr + kk);
        }
        __syncthreads();

        #pragma unroll
        for (int kst = 0; kst < 4; kst++) {
            int k0 = kst * 8;
            uint32_t a[4];
            a[0] = sA[(wrow + gid)     * 36 + k0 + tig];
            a[1] = sA[(wrow + gid + 8) * 36 + k0 + tig];
            a[2] = sA[(wrow + gid)     * 36 + k0 + tig + 4];
            a[3] = sA[(wrow + gid + 8) * 36 + k0 + tig + 4];
            #pragma unroll
            for (int nb = 0; nb < 4; nb++) {
                uint32_t b0 = sB[(ncol0 + nb * 8 + gid) * 36 + k0 + tig];
                uint32_t b1 = sB[(ncol0 + nb * 8 + gid) * 36 + k0 + tig + 4];
                mma_tf32_16n8k8(acc[nb], a, b0, b1);
            }
        }
    }

    // ---- partial s,t dots over this warp's 32 cols ----
    float sp0 = 0.f, sp1 = 0.f, tp0 = 0.f, tp1 = 0.f;
    #pragma unroll
    for (int nb = 0; nb < 4; nb++) {
        int cb = ncol0 + nb * 8 + 2 * tig;
        float a0 = s_a[cb],      a1 = s_a[cb + 1];
        float d0 = s_a[64 + cb], d1 = s_a[64 + cb + 1];
        sp0 += acc[nb][0] * a0 + acc[nb][1] * a1;
        sp1 += acc[nb][2] * a0 + acc[nb][3] * a1;
        tp0 += acc[nb][0] * d0 + acc[nb][1] * d1;
        tp1 += acc[nb][2] * d0 + acc[nb][3] * d1;
    }
    #pragma unroll
    for (int o = 1; o < 4; o <<= 1) {
        sp0 += __shfl_xor_sync(0xffffffffu, sp0, o);
        sp1 += __shfl_xor_sync(0xffffffffu, sp1, o);
        tp0 += __shfl_xor_sync(0xffffffffu, tp0, o);
        tp1 += __shfl_xor_sync(0xffffffffu, tp1, o);
    }

    __syncthreads();
    float* s_part = (float*)sB;          // [128][2]
    if (nh == 1 && tig == 0) {
        s_part[(wrow + gid) * 2]         = sp0;
        s_part[(wrow + gid) * 2 + 1]     = tp0;
        s_part[(wrow + gid + 8) * 2]     = sp1;
        s_part[(wrow + gid + 8) * 2 + 1] = tp1;
    }
    __half* sT = (__half*)sA;            // [64 f][128 m] stride 136
    {
        int rlo = wrow + gid, rhi = rlo + 8;
        #pragma unroll
        for (int nb = 0; nb < 4; nb++) {
            int cb = ncol0 + nb * 8 + 2 * tig;
            sT[cb * 136 + rlo]       = __float2half_rn(acc[nb][0]);
            sT[(cb + 1) * 136 + rlo] = __float2half_rn(acc[nb][1]);
            sT[cb * 136 + rhi]       = __float2half_rn(acc[nb][2]);
            sT[(cb + 1) * 136 + rhi] = __float2half_rn(acc[nb][3]);
        }
    }
    __syncthreads();

    if (nh == 0 && tig == 0) {
        int r0 = wrow + gid, r1 = r0 + 8;
        float s0 = sp0 + s_part[r0 * 2], t0 = tp0 + s_part[r0 * 2 + 1];
        float s1 = sp1 + s_part[r1 * 2], t1 = tp1 + s_part[r1 * 2 + 1];
        int olo = head * N_NODES + m0 + r0, ohi = head * N_NODES + m0 + r1;
        g_esh[olo] = __floats2half2_rn(expf(s0 - ESHIFT), expf(ALPHA * s0 - ESHIFT));
        g_esh[ohi] = __floats2half2_rn(expf(s1 - ESHIFT), expf(ALPHA * s1 - ESHIFT));
        g_ee [olo] = __floats2half2_rn(expf(t0 - ESHIFT), expf(ALPHA * t0 - ESHIFT));
        g_ee [ohi] = __floats2half2_rn(expf(t1 - ESHIFT), expf(ALPHA * t1 - ESHIFT));
    }
    #pragma unroll
    for (int itr = 0; itr < 2; itr++) {
        int idx = itr * 512 + tid;
        int f = idx >> 4, seg = idx & 15;
        uint4 v = *(const uint4*)&sT[f * 136 + seg * 8];
        *(uint4*)&g_hT[(n0 + f) * N_NODES + m0 + seg * 8] = v;
    }
}

// ---------------- kernel 2: aggregation v5 — m32 x 4-way k-split -------------
#define AGO_EE   0u          // 4096 half2 = 16384 B
#define AGO_B    16384u      // 2 x (64 x 136 halves) = 34816 B  (reused as sAcc)
#define AGO_MSK  51200u      // 2 x 512 u32 = 4096 B
#define AGO_RED  55296u      // 4 x 128 f = 2048 B
#define AGO_LI   57344u      // 128 f
#define SMEM_AGG 57856
#define B_STRIDE 17408u
#define ONESB    0x3C003C00u

__global__ __launch_bounds__(512, 1) void aggregate_v5(float* __restrict__ out) {
    extern __shared__ char smem[];
    const uint32_t* st_ee = (const uint32_t*)(smem + AGO_EE);
    uint32_t* smsk  = (uint32_t*)(smem + AGO_MSK);    // [2][512]
    float* sred  = (float*)(smem + AGO_RED);
    float* slinv = (float*)(smem + AGO_LI);
    float* sAcc  = (float*)(smem + AGO_B);

    int tid = threadIdx.x, wid = tid >> 5, lane = tid & 31;
    int gid = lane >> 2, tig = lane & 3;
    int h = blockIdx.x & 3, i0 = (blockIdx.x >> 2) * 128;
    int mg = wid & 3, ks = wid >> 2;                 // 4 m-groups x 4 k-splits
    int wrow = mg * 32;
    int r0 = wrow + gid, r1 = r0 + 8, r2 = r0 + 16, r3 = r0 + 24;

    // stage j-side factor table
    {
        const uint4* src = (const uint4*)&g_ee[h * N_NODES];
        uint4* dst = (uint4*)(smem + AGO_EE);
        dst[tid]       = src[tid];
        dst[tid + 512] = src[tid + 512];
    }
    uint32_t esh0 = *(const uint32_t*)&g_esh[h * N_NODES + i0 + r0];
    uint32_t esh1 = *(const uint32_t*)&g_esh[h * N_NODES + i0 + r1];
    uint32_t esh2 = *(const uint32_t*)&g_esh[h * N_NODES + i0 + r2];
    uint32_t esh3 = *(const uint32_t*)&g_esh[h * N_NODES + i0 + r3];

    float acc[2][8][4], accl[2][4];
    #pragma unroll
    for (int mf = 0; mf < 2; mf++) {
        #pragma unroll
        for (int nb = 0; nb < 8; nb++)
            #pragma unroll
            for (int e = 0; e < 4; e++) acc[mf][nb][e] = 0.f;
        #pragma unroll
        for (int e = 0; e < 4; e++) accl[mf][e] = 0.f;
    }

    // B staging ids (as R8)
    int brow = tid >> 3, bcol = (tid & 7) * 16;
    const __half* hTrow = &g_hT[(h * 64 + brow) * N_NODES];
    uint32_t sb_base = smem_u32(smem + AGO_B);
    int lmrow = (lane & 15) * 136 + (lane >> 4) * 8;

    // mask staging id: word (tid&3) of row (tid>>2)
    int msrow = tid >> 2, msw = tid & 3;
    const uint32_t* adjstage = &g_adjbits[(i0 + msrow) * 128 + msw];

    // stage chunk 0
    {
        uint4 pv0 = *(const uint4*)(hTrow + bcol);
        uint4 pv1 = *(const uint4*)(hTrow + bcol + 8);
        __half* B0 = (__half*)(smem + AGO_B);
        *(uint4*)&B0[brow * 136 + bcol]     = pv0;
        *(uint4*)&B0[brow * 136 + bcol + 8] = pv1;
        smsk[msrow * 4 + msw] = adjstage[0];
    }
    __syncthreads();

    for (int c = 0; c < 32; c++) {
        int b = c & 1;
        uint4 nv0, nv1; uint32_t nmask = 0;
        if (c < 31) {
            const __half* src = hTrow + (c + 1) * 128;
            nv0 = *(const uint4*)(src + bcol);
            nv1 = *(const uint4*)(src + bcol + 8);
            nmask = adjstage[(c + 1) * 4];
        }

        const uint32_t* mk = smsk + b * 512;
        uint32_t mw0 = mk[r0 * 4 + ks], mw1 = mk[r1 * 4 + ks];
        uint32_t mw2 = mk[r2 * 4 + ks], mw3 = mk[r3 * 4 + ks];
        uint32_t bufb = sb_base + b * B_STRIDE;
        int jcb = c * 128 + ks * 32;

        #pragma unroll
        for (int kst = 0; kst < 2; kst++) {
            int kb = ks * 32 + kst * 16;
            // ---- build A-fragments for both m-frags ----
            uint32_t a0[4], a1[4];
            #pragma unroll
            for (int kp = 0; kp < 2; kp++) {
                int koff = kp * 8 + 2 * tig;
                uint2 ee2 = *(const uint2*)(st_ee + jcb + kst * 16 + koff);
                int bit = kst * 16 + koff;
                uint32_t pA, pB, pk, km;
                pA = hmul2u(esh0, ee2.x); pB = hmul2u(esh0, ee2.y);
                pk = hmax2u(__byte_perm(pA, pB, 0x5410), __byte_perm(pA, pB, 0x7632));
                km = (((mw0 >> bit) & 1u) ? 0x0000FFFFu : 0u) |
                     (((mw0 >> bit) & 2u) ? 0xFFFF0000u : 0u);
                a0[2 * kp] = pk & km;
                pA = hmul2u(esh1, ee2.x); pB = hmul2u(esh1, ee2.y);
                pk = hmax2u(__byte_perm(pA, pB, 0x5410), __byte_perm(pA, pB, 0x7632));
                km = (((mw1 >> bit) & 1u) ? 0x0000FFFFu : 0u) |
                     (((mw1 >> bit) & 2u) ? 0xFFFF0000u : 0u);
                a0[2 * kp + 1] = pk & km;
                pA = hmul2u(esh2, ee2.x); pB = hmul2u(esh2, ee2.y);
                pk = hmax2u(__byte_perm(pA, pB, 0x5410), __byte_perm(pA, pB, 0x7632));
                km = (((mw2 >> bit) & 1u) ? 0x0000FFFFu : 0u) |
                     (((mw2 >> bit) & 2u) ? 0xFFFF0000u : 0u);
                a1[2 * kp] = pk & km;
                pA = hmul2u(esh3, ee2.x); pB = hmul2u(esh3, ee2.y);
                pk = hmax2u(__byte_perm(pA, pB, 0x5410), __byte_perm(pA, pB, 0x7632));
                km = (((mw3 >> bit) & 1u) ? 0x0000FFFFu : 0u) |
                     (((mw3 >> bit) & 2u) ? 0xFFFF0000u : 0u);
                a1[2 * kp + 1] = pk & km;
            }
            // ---- B fragments (shared by both m-frags) ----
            uint32_t br[4][4];
            #pragma unroll
            for (int nbp = 0; nbp < 4; nbp++)
                ldmat_x4(br[nbp], bufb + 2u * (uint32_t)(nbp * 16 * 136 + kb + lmrow));
            #pragma unroll
            for (int nb = 0; nb < 8; nb++) {
                int nbp = nb >> 1, hi = nb & 1;
                mma_f16_16n8k16(acc[0][nb], a0, br[nbp][hi], br[nbp][2 + hi]);
                mma_f16_16n8k16(acc[1][nb], a1, br[nbp][hi], br[nbp][2 + hi]);
            }
            mma_f16_16n8k16(accl[0], a0, ONESB, ONESB);
            mma_f16_16n8k16(accl[1], a1, ONESB, ONESB);
        }

        if (c < 31) {
            __half* Bd = (__half*)(smem + AGO_B + (b ^ 1) * B_STRIDE);
            *(uint4*)&Bd[brow * 136 + bcol]     = nv0;
            *(uint4*)&Bd[brow * 136 + bcol + 8] = nv1;
            smsk[(b ^ 1) * 512 + msrow * 4 + msw] = nmask;
        }
        __syncthreads();
    }

    // ---- l from ones-MMA (4-way) ----
    if (tig == 0) {
        sred[ks * 128 + r0] = accl[0][0];
        sred[ks * 128 + r1] = accl[0][2];
        sred[ks * 128 + r2] = accl[1][0];
        sred[ks * 128 + r3] = accl[1][2];
    }
    __syncthreads();
    if (tid < 128)
        slinv[tid] = 1.f / (sred[tid] + sred[128 + tid] + sred[256 + tid] + sred[384 + tid]);

    // ---- 3-round k-split combine through sAcc (reuses B region) ----
    #pragma unroll
    for (int ksrc = 1; ksrc < 4; ksrc++) {
        __syncthreads();
        if (ks == ksrc) {
            #pragma unroll
            for (int mf = 0; mf < 2; mf++) {
                int rlo = wrow + mf * 16 + gid, rhi = rlo + 8;
                #pragma unroll
                for (int nb = 0; nb < 8; nb++) {
                    int cb = nb * 8 + 2 * tig;
                    *(float2*)&sAcc[rlo * 66 + cb] = make_float2(acc[mf][nb][0], acc[mf][nb][1]);
                    *(float2*)&sAcc[rhi * 66 + cb] = make_float2(acc[mf][nb][2], acc[mf][nb][3]);
                }
            }
        }
        __syncthreads();
        if (ks == 0) {
            #pragma unroll
            for (int mf = 0; mf < 2; mf++) {
                int rlo = wrow + mf * 16 + gid, rhi = rlo + 8;
                #pragma unroll
                for (int nb = 0; nb < 8; nb++) {
                    int cb = nb * 8 + 2 * tig;
                    float2 o0 = *(const float2*)&sAcc[rlo * 66 + cb];
                    float2 o1 = *(const float2*)&sAcc[rhi * 66 + cb];
                    acc[mf][nb][0] += o0.x; acc[mf][nb][1] += o0.y;
                    acc[mf][nb][2] += o1.x; acc[mf][nb][3] += o1.y;
                }
            }
        }
    }

    // ---- normalize + store (ks==0 warps own all 128 rows) ----
    if (ks == 0) {
        #pragma unroll
        for (int mf = 0; mf < 2; mf++) {
            int rlo = wrow + mf * 16 + gid, rhi = rlo + 8;
            float invlo = slinv[rlo], invhi = slinv[rhi];
            #pragma unroll
            for (int nb = 0; nb < 8; nb++) {
                int cb = nb * 8 + 2 * tig;
                *(float2*)&out[(i0 + rlo) * C_TOT + h * 64 + cb] =
                    make_float2(acc[mf][nb][0] * invlo, acc[mf][nb][1] * invlo);
                *(float2*)&out[(i0 + rhi) * C_TOT + h * 64 + cb] =
                    make_float2(acc[mf][nb][2] * invhi, acc[mf][nb][3] * invhi);
            }
        }
    }
}

// ---------------- launch ----------------
extern "C" void kernel_launch(void* const* d_in, const int* in_sizes, int n_in,
                              void* d_out, int out_size) {
    const float* x   = (const float*)d_in[0];
    const int*   adj = (const int*)  d_in[1];
    const float* W   = (const float*)d_in[2];
    const float* a   = (const float*)d_in[3];
    float* out = (float*)d_out;

    cudaFuncSetAttribute(aggregate_v5,
                         cudaFuncAttributeMaxDynamicSharedMemorySize, SMEM_AGG);

    pack_adj<<<(N_NODES * N_NODES) / 256, 256>>>(adj);
    transpose_w<<<dim3(IN_F / 32, C_TOT / 32), 256>>>(W);
    gemm_xw_mma<<<dim3(C_TOT / 64, N_NODES / 128), 512>>>(x, a);
    aggregate_v5<<<(N_NODES / 128) * NHEADS, 512, SMEM_AGG>>>(out);
}

// round 11
// speedup vs baseline: 1.0882x; 1.0837x over previous
#include <cuda_runtime.h>
#include <cuda_fp16.h>
#include <cstdint>

#define N_NODES 4096
#define IN_F    512
#define NHEADS  4
#define OUT_F   64
#define C_TOT   256
#define ALPHA   0.2f
#define ESHIFT  2.0f

// ---------------- scratch ----------------
__device__ __half   g_hT  [C_TOT * N_NODES];      // [(h*64+f)][j]  fp16
__device__ float    g_WT  [C_TOT * IN_F];         // W^T, pre-rounded to tf32
__device__ __half2  g_esh [NHEADS * N_NODES];     // (exp(s-2), exp(a*s-2))  i-side
__device__ __half2  g_ee  [NHEADS * N_NODES];     // (exp(t-2), exp(a*t-2))  j-side
__device__ uint32_t g_adjbits[N_NODES * (N_NODES / 32)];

// ---------------- helpers ----------------
__device__ __forceinline__ uint32_t smem_u32(const void* p) {
    uint32_t a;
    asm("{ .reg .u64 t; cvta.to.shared.u64 t, %1; cvt.u32.u64 %0, t; }"
        : "=r"(a) : "l"(p));
    return a;
}
__device__ __forceinline__ uint32_t f2tf32(float f) {
    uint32_t u;
    asm("cvt.rna.tf32.f32 %0, %1;" : "=r"(u) : "f"(f));
    return u;
}
__device__ __forceinline__ uint32_t hmul2u(uint32_t a, uint32_t b) {
    uint32_t r; asm("mul.f16x2 %0, %1, %2;" : "=r"(r) : "r"(a), "r"(b)); return r;
}
__device__ __forceinline__ uint32_t hmax2u(uint32_t a, uint32_t b) {
    uint32_t r; asm("max.f16x2 %0, %1, %2;" : "=r"(r) : "r"(a), "r"(b)); return r;
}
__device__ __forceinline__ void mma_tf32_16n8k8(float* d, const uint32_t* a,
                                                uint32_t b0, uint32_t b1) {
    asm volatile(
        "mma.sync.aligned.m16n8k8.row.col.f32.tf32.tf32.f32 "
        "{%0,%1,%2,%3}, {%4,%5,%6,%7}, {%8,%9}, {%0,%1,%2,%3};"
        : "+f"(d[0]), "+f"(d[1]), "+f"(d[2]), "+f"(d[3])
        : "r"(a[0]), "r"(a[1]), "r"(a[2]), "r"(a[3]), "r"(b0), "r"(b1));
}
__device__ __forceinline__ void mma_f16_16n8k16(float* d, const uint32_t* a,
                                                uint32_t b0, uint32_t b1) {
    asm volatile(
        "mma.sync.aligned.m16n8k16.row.col.f32.f16.f16.f32 "
        "{%0,%1,%2,%3}, {%4,%5,%6,%7}, {%8,%9}, {%0,%1,%2,%3};"
        : "+f"(d[0]), "+f"(d[1]), "+f"(d[2]), "+f"(d[3])
        : "r"(a[0]), "r"(a[1]), "r"(a[2]), "r"(a[3]), "r"(b0), "r"(b1));
}
__device__ __forceinline__ void ldmat_x4(uint32_t* r, uint32_t addr) {
    asm volatile("ldmatrix.sync.aligned.m8n8.x4.shared.b16 {%0,%1,%2,%3}, [%4];"
        : "=r"(r[0]), "=r"(r[1]), "=r"(r[2]), "=r"(r[3]) : "r"(addr));
}

// ---------------- kernel 0: transpose W -> g_WT (pre-tf32) ----------------
__global__ __launch_bounds__(256) void transpose_w(const float* __restrict__ W) {
    __shared__ float t[32][33];
    int kx = blockIdx.x * 32, nx = blockIdx.y * 32;
    int lx = threadIdx.x & 31, ly = threadIdx.x >> 5;
    #pragma unroll
    for (int q = 0; q < 4; q++)
        t[ly + q*8][lx] = W[(kx + ly + q*8) * C_TOT + nx + lx];
    __syncthreads();
    #pragma unroll
    for (int q = 0; q < 4; q++)
        g_WT[(nx + ly + q*8) * IN_F + kx + lx] =
            __uint_as_float(f2tf32(t[lx][ly + q*8]));
}

// ---------------- kernel 1d: pack adj into bits ----------------
__global__ __launch_bounds__(256) void pack_adj(const int* __restrict__ adj) {
    int g = blockIdx.x * 256 + threadIdx.x;
    int w = g >> 5, lane = g & 31;
    int v = adj[w * 32 + lane];
    uint32_t b = __ballot_sync(0xffffffffu, v > 0);
    if (lane == 0) g_adjbits[w] = b;
}

// ---------------- kernel 1: h = x@W (tf32 HMMA, 512 thr) + fused epilogue ----
__global__ __launch_bounds__(512) void gemm_xw_mma(const float* __restrict__ x,
                                                   const float* __restrict__ avec) {
    __shared__ uint32_t sA[128 * 36];     // reused as fp16 sT 64x136
    __shared__ uint32_t sB[64 * 36];      // reused as s_part
    __shared__ float s_a[128];

    int tid = threadIdx.x, wid = tid >> 5, lane = tid & 31;
    int gid = lane >> 2, tig = lane & 3;
    int mg = wid & 7, nh = wid >> 3;
    int wrow = mg * 16, ncol0 = nh * 32;
    int n0 = blockIdx.x * 64, m0 = blockIdx.y * 128;
    int head = blockIdx.x;

    if (tid < 128) s_a[tid] = avec[tid];

    float acc[4][4];
    #pragma unroll
    for (int nb = 0; nb < 4; nb++)
        #pragma unroll
        for (int q = 0; q < 4; q++) acc[nb][q] = 0.f;

    int ar = tid >> 2, aks = (tid & 3) * 8;
    int bn = tid >> 3, bks = (tid & 7) * 4;
    const float* aptr = &x[(m0 + ar) * IN_F + aks];
    const float* bptr = &g_WT[(n0 + bn) * IN_F + bks];

    float4 av[2]; uint4 bv;
    av[0] = *(const float4*)(aptr);
    av[1] = *(const float4*)(aptr + 4);
    bv = *(const uint4*)(bptr);

    for (int it = 0; it < 16; it++) {
        __syncthreads();
        #pragma unroll
        for (int e = 0; e < 2; e++) {
            uint4 u = { f2tf32(av[e].x), f2tf32(av[e].y), f2tf32(av[e].z), f2tf32(av[e].w) };
            *(uint4*)&sA[ar * 36 + aks + 4 * e] = u;
        }
        *(uint4*)&sB[bn * 36 + bks] = bv;
        if (it < 15) {
            int kk = (it + 1) * 32;
            av[0] = *(const float4*)(aptr + kk);
            av[1] = *(const float4*)(aptr + kk + 4);
            bv = *(const uint4*)(bptr + kk);
        }
        __syncthreads();

        #pragma unroll
        for (int kst = 0; kst < 4; kst++) {
            int k0 = kst * 8;
            uint32_t a[4];
            a[0] = sA[(wrow + gid)     * 36 + k0 + tig];
            a[1] = sA[(wrow + gid + 8) * 36 + k0 + tig];
            a[2] = sA[(wrow + gid)     * 36 + k0 + tig + 4];
            a[3] = sA[(wrow + gid + 8) * 36 + k0 + tig + 4];
            #pragma unroll
            for (int nb = 0; nb < 4; nb++) {
                uint32_t b0 = sB[(ncol0 + nb * 8 + gid) * 36 + k0 + tig];
                uint32_t b1 = sB[(ncol0 + nb * 8 + gid) * 36 + k0 + tig + 4];
                mma_tf32_16n8k8(acc[nb], a, b0, b1);
            }
        }
    }

    // ---- partial s,t dots over this warp's 32 cols ----
    float sp0 = 0.f, sp1 = 0.f, tp0 = 0.f, tp1 = 0.f;
    #pragma unroll
    for (int nb = 0; nb < 4; nb++) {
        int cb = ncol0 + nb * 8 + 2 * tig;
        float a0 = s_a[cb],      a1 = s_a[cb + 1];
        float d0 = s_a[64 + cb], d1 = s_a[64 + cb + 1];
        sp0 += acc[nb][0] * a0 + acc[nb][1] * a1;
        sp1 += acc[nb][2] * a0 + acc[nb][3] * a1;
        tp0 += acc[nb][0] * d0 + acc[nb][1] * d1;
        tp1 += acc[nb][2] * d0 + acc[nb][3] * d1;
    }
    #pragma unroll
    for (int o = 1; o < 4; o <<= 1) {
        sp0 += __shfl_xor_sync(0xffffffffu, sp0, o);
        sp1 += __shfl_xor_sync(0xffffffffu, sp1, o);
        tp0 += __shfl_xor_sync(0xffffffffu, tp0, o);
        tp1 += __shfl_xor_sync(0xffffffffu, tp1, o);
    }

    __syncthreads();
    float* s_part = (float*)sB;          // [128][2]
    if (nh == 1 && tig == 0) {
        s_part[(wrow + gid) * 2]         = sp0;
        s_part[(wrow + gid) * 2 + 1]     = tp0;
        s_part[(wrow + gid + 8) * 2]     = sp1;
        s_part[(wrow + gid + 8) * 2 + 1] = tp1;
    }
    __half* sT = (__half*)sA;            // [64 f][128 m] stride 136
    {
        int rlo = wrow + gid, rhi = rlo + 8;
        #pragma unroll
        for (int nb = 0; nb < 4; nb++) {
            int cb = ncol0 + nb * 8 + 2 * tig;
            sT[cb * 136 + rlo]       = __float2half_rn(acc[nb][0]);
            sT[(cb + 1) * 136 + rlo] = __float2half_rn(acc[nb][1]);
            sT[cb * 136 + rhi]       = __float2half_rn(acc[nb][2]);
            sT[(cb + 1) * 136 + rhi] = __float2half_rn(acc[nb][3]);
        }
    }
    __syncthreads();

    if (nh == 0 && tig == 0) {
        int r0 = wrow + gid, r1 = r0 + 8;
        float s0 = sp0 + s_part[r0 * 2], t0 = tp0 + s_part[r0 * 2 + 1];
        float s1 = sp1 + s_part[r1 * 2], t1 = tp1 + s_part[r1 * 2 + 1];
        int olo = head * N_NODES + m0 + r0, ohi = head * N_NODES + m0 + r1;
        g_esh[olo] = __floats2half2_rn(expf(s0 - ESHIFT), expf(ALPHA * s0 - ESHIFT));
        g_esh[ohi] = __floats2half2_rn(expf(s1 - ESHIFT), expf(ALPHA * s1 - ESHIFT));
        g_ee [olo] = __floats2half2_rn(expf(t0 - ESHIFT), expf(ALPHA * t0 - ESHIFT));
        g_ee [ohi] = __floats2half2_rn(expf(t1 - ESHIFT), expf(ALPHA * t1 - ESHIFT));
    }
    #pragma unroll
    for (int itr = 0; itr < 2; itr++) {
        int idx = itr * 512 + tid;
        int f = idx >> 4, seg = idx & 15;
        uint4 v = *(const uint4*)&sT[f * 136 + seg * 8];
        *(uint4*)&g_hT[(n0 + f) * N_NODES + m0 + seg * 8] = v;
    }
}

// ---------------- kernel 2: aggregation v6 = R8-v3 + pair-major ee table -----
// smem table repacked at staging: per j-pair p -> uint2{(Et_j0,Et_j1),(Eat_j0,Eat_j1)}
#define AGO_EE   0u          // 2048 uint2 = 16384 B
#define AGO_B    16384u      // 2 x (64 x 136 halves) = 34816 B (reused as sAcc)
#define AGO_RED  51200u      // 2 x 128 f
#define AGO_LI   52224u      // 128 f
#define SMEM_AGG 52736
#define B_STRIDE 17408u
#define ONESB    0x3C003C00u

__global__ __launch_bounds__(512, 1) void aggregate_v6(float* __restrict__ out) {
    extern __shared__ char smem[];
    const uint2* st_eeP = (const uint2*)(smem + AGO_EE);
    float* sred  = (float*)(smem + AGO_RED);
    float* slinv = (float*)(smem + AGO_LI);
    float* sAcc  = (float*)(smem + AGO_B);      // reused after main loop

    int tid = threadIdx.x, wid = tid >> 5, lane = tid & 31;
    int gid = lane >> 2, tig = lane & 3;
    int h = blockIdx.x & 3, i0 = (blockIdx.x >> 2) * 128;
    int mg = wid & 7, ks = wid >> 3;
    int wrow = mg * 16, r0 = wrow + gid, r1 = r0 + 8;

    // stage j-side factor table, repacked to pair-major (one-time PRMTs)
    {
        const uint4* src = (const uint4*)&g_ee[h * N_NODES];
        uint4* dst = (uint4*)(smem + AGO_EE);
        #pragma unroll
        for (int q = 0; q < 2; q++) {
            uint4 v = src[tid + q * 512];
            uint4 o;
            o.x = __byte_perm(v.x, v.y, 0x5410);   // (Et0,  Et1)
            o.y = __byte_perm(v.x, v.y, 0x7632);   // (Eat0, Eat1)
            o.z = __byte_perm(v.z, v.w, 0x5410);
            o.w = __byte_perm(v.z, v.w, 0x7632);
            dst[tid + q * 512] = o;
        }
    }
    uint32_t esh0 = *(const uint32_t*)&g_esh[h * N_NODES + i0 + r0];
    uint32_t esh1 = *(const uint32_t*)&g_esh[h * N_NODES + i0 + r1];
    uint32_t eshE0 = __byte_perm(esh0, esh0, 0x1010);   // (es0, es0)
    uint32_t eshA0 = __byte_perm(esh0, esh0, 0x3232);   // (eas0,eas0)
    uint32_t eshE1 = __byte_perm(esh1, esh1, 0x1010);
    uint32_t eshA1 = __byte_perm(esh1, esh1, 0x3232);
    const uint32_t* mr0 = &g_adjbits[(i0 + r0) * 128 + 2 * ks];
    const uint32_t* mr1 = &g_adjbits[(i0 + r1) * 128 + 2 * ks];

    float acc[8][4], accl[4];
    #pragma unroll
    for (int nb = 0; nb < 8; nb++)
        #pragma unroll
        for (int e = 0; e < 4; e++) acc[nb][e] = 0.f;
    #pragma unroll
    for (int e = 0; e < 4; e++) accl[e] = 0.f;

    // B staging ids
    int brow = tid >> 3, bcol = (tid & 7) * 16;
    const __half* hTrow = &g_hT[(h * 64 + brow) * N_NODES];
    uint32_t sb_base = smem_u32(smem + AGO_B);
    int lmrow = (lane & 15) * 136 + (lane >> 4) * 8;

    uint2 mw0 = *(const uint2*)mr0;
    uint2 mw1 = *(const uint2*)mr1;
    {
        uint4 pv0 = *(const uint4*)(hTrow + bcol);
        uint4 pv1 = *(const uint4*)(hTrow + bcol + 8);
        __half* B0 = (__half*)(smem + AGO_B);
        *(uint4*)&B0[brow * 136 + bcol]     = pv0;
        *(uint4*)&B0[brow * 136 + bcol + 8] = pv1;
    }
    __syncthreads();

    for (int c = 0; c < 32; c++) {
        int b = c & 1;
        uint4 nv0, nv1; uint2 nm0, nm1;
        if (c < 31) {
            const __half* src = hTrow + (c + 1) * 128;
            nv0 = *(const uint4*)(src + bcol);
            nv1 = *(const uint4*)(src + bcol + 8);
            nm0 = *(const uint2*)(mr0 + 4 * (c + 1));
            nm1 = *(const uint2*)(mr1 + 4 * (c + 1));
        }

        // ---- build A-fragments: p = max(es*Et, eas*Eat), pair-major, no PRMT
        uint32_t afr[4][4];
        int pc = c * 64 + ks * 32;          // j-pair base for this chunk/k-split
        #pragma unroll
        for (int kst = 0; kst < 4; kst++) {
            uint32_t w0 = (kst & 2) ? mw0.y : mw0.x;
            uint32_t w1 = (kst & 2) ? mw1.y : mw1.x;
            #pragma unroll
            for (int kp = 0; kp < 2; kp++) {
                int koff = kp * 8 + 2 * tig;              // 0..14 even
                uint2 ee = st_eeP[pc + kst * 8 + kp * 4 + tig];
                int bit = ((kst & 1) * 16) + koff;
                uint32_t pk = hmax2u(hmul2u(eshE0, ee.x), hmul2u(eshA0, ee.y));
                uint32_t km = (((w0 >> bit) & 1u) ? 0x0000FFFFu : 0u) |
                              (((w0 >> bit) & 2u) ? 0xFFFF0000u : 0u);
                afr[kst][2 * kp] = pk & km;
                pk = hmax2u(hmul2u(eshE1, ee.x), hmul2u(eshA1, ee.y));
                km = (((w1 >> bit) & 1u) ? 0x0000FFFFu : 0u) |
                     (((w1 >> bit) & 2u) ? 0xFFFF0000u : 0u);
                afr[kst][2 * kp + 1] = pk & km;
            }
        }

        // ---- MMA from buf b via ldmatrix (+ ones-MMA for row sums) ----
        {
            uint32_t bufb = sb_base + b * B_STRIDE;
            #pragma unroll
            for (int kst = 0; kst < 4; kst++) {
                int kb = ks * 64 + kst * 16;
                uint32_t br[4][4];
                #pragma unroll
                for (int nbp = 0; nbp < 4; nbp++)
                    ldmat_x4(br[nbp], bufb + 2u * (uint32_t)(nbp * 16 * 136 + kb + lmrow));
                #pragma unroll
                for (int nb = 0; nb < 8; nb++) {
                    int nbp = nb >> 1, hi = nb & 1;
                    mma_f16_16n8k16(acc[nb], afr[kst], br[nbp][hi], br[nbp][2 + hi]);
                }
                mma_f16_16n8k16(accl, afr[kst], ONESB, ONESB);
            }
        }

        if (c < 31) {
            __half* Bd = (__half*)(smem + AGO_B + (b ^ 1) * B_STRIDE);
            *(uint4*)&Bd[brow * 136 + bcol]     = nv0;
            *(uint4*)&Bd[brow * 136 + bcol + 8] = nv1;
            mw0 = nm0; mw1 = nm1;
        }
        __syncthreads();
    }

    // ---- l from ones-MMA + k-split combine ----
    if (tig == 0) {
        sred[ks * 128 + r0] = accl[0];
        sred[ks * 128 + r1] = accl[2];
    }
    if (ks == 1) {
        #pragma unroll
        for (int nb = 0; nb < 8; nb++) {
            int cb = nb * 8 + 2 * tig;
            *(float2*)&sAcc[r0 * 66 + cb] = make_float2(acc[nb][0], acc[nb][1]);
            *(float2*)&sAcc[r1 * 66 + cb] = make_float2(acc[nb][2], acc[nb][3]);
        }
    }
    __syncthreads();
    if (tid < 128) slinv[tid] = 1.f / (sred[tid] + sred[128 + tid]);
    __syncthreads();

    if (ks == 0) {
        float inv0 = slinv[r0], inv1 = slinv[r1];
        #pragma unroll
        for (int nb = 0; nb < 8; nb++) {
            int cb = nb * 8 + 2 * tig;
            float2 o0 = *(const float2*)&sAcc[r0 * 66 + cb];
            float2 o1 = *(const float2*)&sAcc[r1 * 66 + cb];
            float2 v0 = make_float2((acc[nb][0] + o0.x) * inv0, (acc[nb][1] + o0.y) * inv0);
            float2 v1 = make_float2((acc[nb][2] + o1.x) * inv1, (acc[nb][3] + o1.y) * inv1);
            *(float2*)&out[(i0 + r0) * C_TOT + h * 64 + cb] = v0;
            *(float2*)&out[(i0 + r1) * C_TOT + h * 64 + cb] = v1;
        }
    }
}

// ---------------- launch: fork pack_adj parallel to transpose_w->gemm --------
extern "C" void kernel_launch(void* const* d_in, const int* in_sizes, int n_in,
                              void* d_out, int out_size) {
    const float* x   = (const float*)d_in[0];
    const int*   adj = (const int*)  d_in[1];
    const float* W   = (const float*)d_in[2];
    const float* a   = (const float*)d_in[3];
    float* out = (float*)d_out;

    static cudaStream_t s2 = nullptr;
    static cudaEvent_t evF = nullptr, evJ = nullptr;
    if (!s2) {
        cudaStreamCreate(&s2);
        cudaEventCreateWithFlags(&evF, cudaEventDisableTiming);
        cudaEventCreateWithFlags(&evJ, cudaEventDisableTiming);
        cudaFuncSetAttribute(aggregate_v6,
                             cudaFuncAttributeMaxDynamicSharedMemorySize, SMEM_AGG);
    }

    cudaEventRecord(evF, 0);
    cudaStreamWaitEvent(s2, evF, 0);
    pack_adj<<<(N_NODES * N_NODES) / 256, 256, 0, s2>>>(adj);

    transpose_w<<<dim3(IN_F / 32, C_TOT / 32), 256>>>(W);
    gemm_xw_mma<<<dim3(C_TOT / 64, N_NODES / 128), 512>>>(x, a);

    cudaEventRecord(evJ, s2);
    cudaStreamWaitEvent(0, evJ, 0);
    aggregate_v6<<<(N_NODES / 128) * NHEADS, 512, SMEM_AGG>>>(out);
}